// round 16
// baseline (speedup 1.0000x reference)
#include <cuda_runtime.h>
#include <cuda_bf16.h>

#define N_ROWS 8192
#define F_DIM  512
#define K_KEEP 4096
#define G_A    4096
#define G_X    2048
#define GRID2  (G_A + G_X)

// Scratch (device globals — no allocation allowed)
__device__ __align__(16) float g_y[N_ROWS];
__device__ float               g_inv_norm;
__device__ __align__(16) int   g_idx[K_KEEP];

// ---------------------------------------------------------------------------
// Kernel A: y[row] = dot(X[row], kernel). One warp per row.
// grid = 1024, block = 256.  (proven 6.66 µs config — do not touch)
// ---------------------------------------------------------------------------
__global__ __launch_bounds__(256) void compute_y_kernel(
    const float* __restrict__ X, const float* __restrict__ kern)
{
    int warp = threadIdx.x >> 5;
    int lane = threadIdx.x & 31;
    int row  = blockIdx.x * 8 + warp;
    const float4* x4 = (const float4*)(X + (size_t)row * F_DIM);
    const float4* k4 = (const float4*)kern;
    float acc = 0.f;
#pragma unroll
    for (int it = 0; it < 4; it++) {
        int j = lane + 32 * it;
        float4 x = x4[j];
        float4 k = __ldg(&k4[j]);
        acc = fmaf(x.x, k.x, acc);
        acc = fmaf(x.y, k.y, acc);
        acc = fmaf(x.z, k.z, acc);
        acc = fmaf(x.w, k.w, acc);
    }
#pragma unroll
    for (int o = 16; o > 0; o >>= 1)
        acc += __shfl_xor_sync(0xFFFFFFFFu, acc, o);
    if (lane == 0) g_y[row] = acc;
}

// ---------------------------------------------------------------------------
// Block scans (1024 threads, 32 warps)
// ---------------------------------------------------------------------------
__device__ __forceinline__ int block_exscan(int v, int* s_warp)
{
    __syncthreads();
    int lane = threadIdx.x & 31, warp = threadIdx.x >> 5;
    int incl = v;
#pragma unroll
    for (int o = 1; o < 32; o <<= 1) {
        int t = __shfl_up_sync(0xFFFFFFFFu, incl, o);
        if (lane >= o) incl += t;
    }
    if (lane == 31) s_warp[warp] = incl;
    __syncthreads();
    if (warp == 0) {
        int w  = s_warp[lane];
        int wi = w;
#pragma unroll
        for (int o = 1; o < 32; o <<= 1) {
            int t = __shfl_up_sync(0xFFFFFFFFu, wi, o);
            if (lane >= o) wi += t;
        }
        s_warp[lane] = wi - w;
    }
    __syncthreads();
    return s_warp[warp] + incl - v;
}

__device__ __forceinline__ int block_exscan_tot(int v, int* s_warp, int* s_tot)
{
    __syncthreads();
    int lane = threadIdx.x & 31, warp = threadIdx.x >> 5;
    int incl = v;
#pragma unroll
    for (int o = 1; o < 32; o <<= 1) {
        int t = __shfl_up_sync(0xFFFFFFFFu, incl, o);
        if (lane >= o) incl += t;
    }
    if (lane == 31) s_warp[warp] = incl;
    __syncthreads();
    if (warp == 0) {
        int w  = s_warp[lane];
        int wi = w;
#pragma unroll
        for (int o = 1; o < 32; o <<= 1) {
            int t = __shfl_up_sync(0xFFFFFFFFu, wi, o);
            if (lane >= o) wi += t;
        }
        if (lane == 31) *s_tot = wi;
        s_warp[lane] = wi - w;
    }
    __syncthreads();
    return s_warp[warp] + incl - v;
}

// ---------------------------------------------------------------------------
// Kernel B: single block, 1024 threads. One smem histogram pass (top 11 bits),
// suffix scan, crossing-bin candidate ranking; 3-pass radix fallback for
// pathological ties. Emits idx[] ascending + inv_norm.
// ---------------------------------------------------------------------------
__global__ __launch_bounds__(1024) void select_kernel(const float* __restrict__ kern)
{
    __shared__ int h[2048];
    __shared__ int s_warp[32];
    __shared__ int s_tot;
    __shared__ float s_red[32];
    __shared__ unsigned s_B;
    __shared__ int s_after;
    __shared__ int s_cc;
    __shared__ unsigned s_ckey[256];
    __shared__ int s_cidx[256];
    __shared__ unsigned s_Tkey;
    __shared__ int s_Tidx;

    int tid  = threadIdx.x;
    int lane = tid & 31, warp = tid >> 5;

    if (tid == 0) s_cc = 0;

    // load 8 keys/thread (contiguous cols tid*8 .. +7)
    const float4* y4 = (const float4*)g_y;
    float4 a = y4[tid * 2 + 0];
    float4 b = y4[tid * 2 + 1];
    float vv[8] = {a.x, a.y, a.z, a.w, b.x, b.y, b.z, b.w};
    unsigned key[8];
#pragma unroll
    for (int j = 0; j < 8; j++) {
        unsigned u = __float_as_uint(vv[j]);
        key[j] = (u & 0x80000000u) ? ~u : (u | 0x80000000u);
    }

    // inv_norm
    {
        float s = 0.f;
        if (tid < F_DIM) { float kv = kern[tid]; s = kv * kv; }
#pragma unroll
        for (int o = 16; o > 0; o >>= 1) s += __shfl_xor_sync(0xFFFFFFFFu, s, o);
        if (lane == 0) s_red[warp] = s;
        __syncthreads();
        if (warp == 0) {
            float t = s_red[lane];
#pragma unroll
            for (int o = 16; o > 0; o >>= 1) t += __shfl_xor_sync(0xFFFFFFFFu, t, o);
            if (lane == 0) s_red[0] = rsqrtf(t);
        }
        __syncthreads();
        if (tid == 0) g_inv_norm = s_red[0];
    }

    // smem histogram over top 11 bits
    h[tid] = 0; h[tid + 1024] = 0;
    __syncthreads();
#pragma unroll
    for (int j = 0; j < 8; j++)
        atomicAdd(&h[key[j] >> 21], 1);
    __syncthreads();

    // suffix-scan 2048 bins (2/thread); find crossing bin
    int v0 = h[2 * tid], v1 = h[2 * tid + 1];
    int ex = block_exscan_tot(v0 + v1, s_warp, &s_tot);
    {
        int suf0 = s_tot - ex;
        int suf1 = suf0 - v0;
        int suf2 = suf1 - v1;
        if (suf0 >= K_KEEP && suf1 < K_KEEP) { s_B = 2u * tid + 0; s_after = suf1; }
        if (suf1 >= K_KEEP && suf2 < K_KEEP) { s_B = 2u * tid + 1; s_after = suf2; }
    }
    __syncthreads();
    unsigned B = s_B;
    int krem = K_KEEP - s_after;

    // collect bin-B candidates
#pragma unroll
    for (int j = 0; j < 8; j++) {
        if ((key[j] >> 21) == B) {
            int p = atomicAdd(&s_cc, 1);
            if (p < 256) { s_ckey[p] = key[j]; s_cidx[p] = tid * 8 + j; }
        }
    }
    __syncthreads();
    int cc = s_cc;

    bool keep[8];
    int mykeep = 0;

    if (cc <= 256) {
        // exact rank of each candidate under (key desc, idx asc)
        if (tid < cc) {
            unsigned k0 = s_ckey[tid]; int i0 = s_cidx[tid];
            int rank = 0;
            for (int j = 0; j < cc; j++) {
                unsigned kj = s_ckey[j]; int ij = s_cidx[j];
                if (kj > k0 || (kj == k0 && ij < i0)) rank++;
            }
            if (rank == krem - 1) { s_Tkey = k0; s_Tidx = i0; }
        }
        __syncthreads();
        unsigned Tkey = s_Tkey; int Tidx = s_Tidx;
#pragma unroll
        for (int j = 0; j < 8; j++) {
            int gi = tid * 8 + j;
            keep[j] = (key[j] > Tkey) || (key[j] == Tkey && gi <= Tidx);
            mykeep += keep[j];
        }
    } else {
        // fallback: full 3-pass radix select (never hit on Gaussian scores)
        const int shifts[3] = {21, 10, 0};
        const int nbv[3]    = {2048, 2048, 1024};
        unsigned prefix = 0, maskdone = 0;
        int kr = K_KEEP;
#pragma unroll 1
        for (int p = 0; p < 3; p++) {
            int nb = nbv[p];
            int shift = shifts[p];
            unsigned bmask = (unsigned)(nb - 1);
            h[tid] = 0; h[tid + 1024] = 0;
            __syncthreads();
#pragma unroll
            for (int j = 0; j < 8; j++)
                if ((key[j] & maskdone) == prefix)
                    atomicAdd(&h[(key[j] >> shift) & bmask], 1);
            __syncthreads();
            if (nb == 2048) {
                int w0 = h[2 * tid], w1 = h[2 * tid + 1];
                int ex2 = block_exscan_tot(w0 + w1, s_warp, &s_tot);
                int suf0 = s_tot - ex2;
                int suf1 = suf0 - w0;
                int suf2 = suf1 - w1;
                if (suf0 >= kr && suf1 < kr) { s_B = 2u*tid + 0; s_after = suf1; }
                if (suf1 >= kr && suf2 < kr) { s_B = 2u*tid + 1; s_after = suf2; }
            } else {
                int w0 = h[tid];
                int ex2 = block_exscan_tot(w0, s_warp, &s_tot);
                int suf0 = s_tot - ex2;
                int suf1 = suf0 - w0;
                if (suf0 >= kr && suf1 < kr) { s_B = (unsigned)tid; s_after = suf1; }
            }
            __syncthreads();
            prefix   |= s_B << shift;
            maskdone |= bmask << shift;
            kr       -= s_after;
            __syncthreads();
        }
        unsigned T = prefix;
        int tie_keep = kr;
        int myeq = 0;
#pragma unroll
        for (int j = 0; j < 8; j++) myeq += (key[j] == T);
        int eq_before = block_exscan(myeq, s_warp);
        int e = eq_before;
#pragma unroll
        for (int j = 0; j < 8; j++) {
            if (key[j] == T) { keep[j] = (e < tie_keep); e++; }
            else             { keep[j] = (key[j] > T); }
            mykeep += keep[j];
        }
    }

    // positions + emit ascending
    int pos = block_exscan(mykeep, s_warp);
#pragma unroll
    for (int j = 0; j < 8; j++)
        if (keep[j]) g_idx[pos++] = tid * 8 + j;
}

// ---------------------------------------------------------------------------
// Kernel C: fused gather (proven 31.1 µs config — do not touch).
//   blocks [0, 4096):      A_pooled — one A-row per block
//   blocks [4096, 6144):   X_pooled — 2 rows per block, tanh gating
// ---------------------------------------------------------------------------
__global__ __launch_bounds__(256) void gather_kernel(
    const float* __restrict__ X, const float* __restrict__ A,
    float* __restrict__ out)
{
    int bid = blockIdx.x;
    int tid = threadIdx.x;
    if (bid < G_A) {
        int r = bid;
        const float* rowp = A + (size_t)g_idx[r] * N_ROWS;
        const int4* idx4 = (const int4*)g_idx;
        float4* o = (float4*)(out + (size_t)K_KEEP * F_DIM + (size_t)r * K_KEEP);
#pragma unroll 4
        for (int it = 0; it < 4; it++) {
            int c = tid + it * 256;
            int4 i = __ldg(&idx4[c]);
            float4 v;
            v.x = __ldg(&rowp[i.x]);
            v.y = __ldg(&rowp[i.y]);
            v.z = __ldg(&rowp[i.z]);
            v.w = __ldg(&rowp[i.w]);
            o[c] = v;
        }
    } else {
        int r   = (bid - G_A) * 2 + (tid >> 7);
        int t   = tid & 127;
        int row = g_idx[r];
        float gate = tanhf(g_y[row] * g_inv_norm);
        const float4* xr = (const float4*)(X + (size_t)row * F_DIM);
        float4* o = (float4*)(out + (size_t)r * F_DIM);
        float4 x = xr[t];
        o[t] = make_float4(x.x * gate, x.y * gate, x.z * gate, x.w * gate);
    }
}

// ---------------------------------------------------------------------------
extern "C" void kernel_launch(void* const* d_in, const int* in_sizes, int n_in,
                              void* d_out, int out_size)
{
    const float* X    = (const float*)d_in[0];
    const float* A    = (const float*)d_in[1];
    const float* kern = (const float*)d_in[2];
    float* out = (float*)d_out;

    compute_y_kernel<<<N_ROWS / 8, 256>>>(X, kern);
    select_kernel<<<1, 1024>>>(kern);
    gather_kernel<<<GRID2, 256>>>(X, A, out);
}

// round 17
// speedup vs baseline: 1.1348x; 1.1348x over previous
#include <cuda_runtime.h>
#include <cuda_bf16.h>

#define N_ROWS 8192
#define F_DIM  512
#define K_KEEP 4096
#define G_A    4096
#define G_X    2048
#define GRID2  (G_A + G_X)

// Scratch (device globals — no allocation allowed)
__device__ __align__(16) float g_y[N_ROWS];
__device__ float               g_inv_norm;
__device__ __align__(16) int   g_idx[K_KEEP];

// ---------------------------------------------------------------------------
// Kernel A: y[row] = dot(X[row], kernel). One warp per row.
// grid = 1024, block = 256.  (round-2 proven config)
// ---------------------------------------------------------------------------
__global__ __launch_bounds__(256) void compute_y_kernel(
    const float* __restrict__ X, const float* __restrict__ kern)
{
    int warp = threadIdx.x >> 5;
    int lane = threadIdx.x & 31;
    int row  = blockIdx.x * 8 + warp;
    const float4* x4 = (const float4*)(X + (size_t)row * F_DIM);
    const float4* k4 = (const float4*)kern;
    float acc = 0.f;
#pragma unroll
    for (int it = 0; it < 4; it++) {
        int j = lane + 32 * it;
        float4 x = x4[j];
        float4 k = __ldg(&k4[j]);
        acc = fmaf(x.x, k.x, acc);
        acc = fmaf(x.y, k.y, acc);
        acc = fmaf(x.z, k.z, acc);
        acc = fmaf(x.w, k.w, acc);
    }
#pragma unroll
    for (int o = 16; o > 0; o >>= 1)
        acc += __shfl_xor_sync(0xFFFFFFFFu, acc, o);
    if (lane == 0) g_y[row] = acc;
}

// ---------------------------------------------------------------------------
// Block scans (1024 threads, 32 warps)
// ---------------------------------------------------------------------------
__device__ __forceinline__ int block_exscan(int v, int* s_warp)
{
    __syncthreads();
    int lane = threadIdx.x & 31, warp = threadIdx.x >> 5;
    int incl = v;
#pragma unroll
    for (int o = 1; o < 32; o <<= 1) {
        int t = __shfl_up_sync(0xFFFFFFFFu, incl, o);
        if (lane >= o) incl += t;
    }
    if (lane == 31) s_warp[warp] = incl;
    __syncthreads();
    if (warp == 0) {
        int w  = s_warp[lane];
        int wi = w;
#pragma unroll
        for (int o = 1; o < 32; o <<= 1) {
            int t = __shfl_up_sync(0xFFFFFFFFu, wi, o);
            if (lane >= o) wi += t;
        }
        s_warp[lane] = wi - w;
    }
    __syncthreads();
    return s_warp[warp] + incl - v;
}

__device__ __forceinline__ int block_exscan_tot(int v, int* s_warp, int* s_tot)
{
    __syncthreads();
    int lane = threadIdx.x & 31, warp = threadIdx.x >> 5;
    int incl = v;
#pragma unroll
    for (int o = 1; o < 32; o <<= 1) {
        int t = __shfl_up_sync(0xFFFFFFFFu, incl, o);
        if (lane >= o) incl += t;
    }
    if (lane == 31) s_warp[warp] = incl;
    __syncthreads();
    if (warp == 0) {
        int w  = s_warp[lane];
        int wi = w;
#pragma unroll
        for (int o = 1; o < 32; o <<= 1) {
            int t = __shfl_up_sync(0xFFFFFFFFu, wi, o);
            if (lane >= o) wi += t;
        }
        if (lane == 31) *s_tot = wi;
        s_warp[lane] = wi - w;
    }
    __syncthreads();
    return s_warp[warp] + incl - v;
}

// ---------------------------------------------------------------------------
// Kernel B: single block, 1024 threads. One smem histogram pass (top 11 bits),
// suffix scan, crossing-bin candidate ranking; 3-pass radix fallback for
// pathological ties. Emits idx[] ascending + inv_norm. (validated r12/r16)
// ---------------------------------------------------------------------------
__global__ __launch_bounds__(1024) void select_kernel(const float* __restrict__ kern)
{
    cudaGridDependencySynchronize();   // PDL: wait for compute_y completion

    __shared__ int h[2048];
    __shared__ int s_warp[32];
    __shared__ int s_tot;
    __shared__ float s_red[32];
    __shared__ unsigned s_B;
    __shared__ int s_after;
    __shared__ int s_cc;
    __shared__ unsigned s_ckey[256];
    __shared__ int s_cidx[256];
    __shared__ unsigned s_Tkey;
    __shared__ int s_Tidx;

    int tid  = threadIdx.x;
    int lane = tid & 31, warp = tid >> 5;

    if (tid == 0) s_cc = 0;

    // load 8 keys/thread (contiguous cols tid*8 .. +7)
    const float4* y4 = (const float4*)g_y;
    float4 a = y4[tid * 2 + 0];
    float4 b = y4[tid * 2 + 1];
    float vv[8] = {a.x, a.y, a.z, a.w, b.x, b.y, b.z, b.w};
    unsigned key[8];
#pragma unroll
    for (int j = 0; j < 8; j++) {
        unsigned u = __float_as_uint(vv[j]);
        key[j] = (u & 0x80000000u) ? ~u : (u | 0x80000000u);
    }

    // inv_norm
    {
        float s = 0.f;
        if (tid < F_DIM) { float kv = kern[tid]; s = kv * kv; }
#pragma unroll
        for (int o = 16; o > 0; o >>= 1) s += __shfl_xor_sync(0xFFFFFFFFu, s, o);
        if (lane == 0) s_red[warp] = s;
        __syncthreads();
        if (warp == 0) {
            float t = s_red[lane];
#pragma unroll
            for (int o = 16; o > 0; o >>= 1) t += __shfl_xor_sync(0xFFFFFFFFu, t, o);
            if (lane == 0) s_red[0] = rsqrtf(t);
        }
        __syncthreads();
        if (tid == 0) g_inv_norm = s_red[0];
    }

    // smem histogram over top 11 bits
    h[tid] = 0; h[tid + 1024] = 0;
    __syncthreads();
#pragma unroll
    for (int j = 0; j < 8; j++)
        atomicAdd(&h[key[j] >> 21], 1);
    __syncthreads();

    // suffix-scan 2048 bins (2/thread); find crossing bin
    int v0 = h[2 * tid], v1 = h[2 * tid + 1];
    int ex = block_exscan_tot(v0 + v1, s_warp, &s_tot);
    {
        int suf0 = s_tot - ex;
        int suf1 = suf0 - v0;
        int suf2 = suf1 - v1;
        if (suf0 >= K_KEEP && suf1 < K_KEEP) { s_B = 2u * tid + 0; s_after = suf1; }
        if (suf1 >= K_KEEP && suf2 < K_KEEP) { s_B = 2u * tid + 1; s_after = suf2; }
    }
    __syncthreads();
    unsigned B = s_B;
    int krem = K_KEEP - s_after;

    // collect bin-B candidates
#pragma unroll
    for (int j = 0; j < 8; j++) {
        if ((key[j] >> 21) == B) {
            int p = atomicAdd(&s_cc, 1);
            if (p < 256) { s_ckey[p] = key[j]; s_cidx[p] = tid * 8 + j; }
        }
    }
    __syncthreads();
    int cc = s_cc;

    bool keep[8];
    int mykeep = 0;

    if (cc <= 256) {
        // exact rank of each candidate under (key desc, idx asc)
        if (tid < cc) {
            unsigned k0 = s_ckey[tid]; int i0 = s_cidx[tid];
            int rank = 0;
            for (int j = 0; j < cc; j++) {
                unsigned kj = s_ckey[j]; int ij = s_cidx[j];
                if (kj > k0 || (kj == k0 && ij < i0)) rank++;
            }
            if (rank == krem - 1) { s_Tkey = k0; s_Tidx = i0; }
        }
        __syncthreads();
        unsigned Tkey = s_Tkey; int Tidx = s_Tidx;
#pragma unroll
        for (int j = 0; j < 8; j++) {
            int gi = tid * 8 + j;
            keep[j] = (key[j] > Tkey) || (key[j] == Tkey && gi <= Tidx);
            mykeep += keep[j];
        }
    } else {
        // fallback: full 3-pass radix select (never hit on Gaussian scores)
        const int shifts[3] = {21, 10, 0};
        const int nbv[3]    = {2048, 2048, 1024};
        unsigned prefix = 0, maskdone = 0;
        int kr = K_KEEP;
#pragma unroll 1
        for (int p = 0; p < 3; p++) {
            int nb = nbv[p];
            int shift = shifts[p];
            unsigned bmask = (unsigned)(nb - 1);
            h[tid] = 0; h[tid + 1024] = 0;
            __syncthreads();
#pragma unroll
            for (int j = 0; j < 8; j++)
                if ((key[j] & maskdone) == prefix)
                    atomicAdd(&h[(key[j] >> shift) & bmask], 1);
            __syncthreads();
            if (nb == 2048) {
                int w0 = h[2 * tid], w1 = h[2 * tid + 1];
                int ex2 = block_exscan_tot(w0 + w1, s_warp, &s_tot);
                int suf0 = s_tot - ex2;
                int suf1 = suf0 - w0;
                int suf2 = suf1 - w1;
                if (suf0 >= kr && suf1 < kr) { s_B = 2u*tid + 0; s_after = suf1; }
                if (suf1 >= kr && suf2 < kr) { s_B = 2u*tid + 1; s_after = suf2; }
            } else {
                int w0 = h[tid];
                int ex2 = block_exscan_tot(w0, s_warp, &s_tot);
                int suf0 = s_tot - ex2;
                int suf1 = suf0 - w0;
                if (suf0 >= kr && suf1 < kr) { s_B = (unsigned)tid; s_after = suf1; }
            }
            __syncthreads();
            prefix   |= s_B << shift;
            maskdone |= bmask << shift;
            kr       -= s_after;
            __syncthreads();
        }
        unsigned T = prefix;
        int tie_keep = kr;
        int myeq = 0;
#pragma unroll
        for (int j = 0; j < 8; j++) myeq += (key[j] == T);
        int eq_before = block_exscan(myeq, s_warp);
        int e = eq_before;
#pragma unroll
        for (int j = 0; j < 8; j++) {
            if (key[j] == T) { keep[j] = (e < tie_keep); e++; }
            else             { keep[j] = (key[j] > T); }
            mykeep += keep[j];
        }
    }

    // positions + emit ascending
    int pos = block_exscan(mykeep, s_warp);
#pragma unroll
    for (int j = 0; j < 8; j++)
        if (keep[j]) g_idx[pos++] = tid * 8 + j;
}

// ---------------------------------------------------------------------------
// Kernel C: fused gather (round-2 proven config).
//   blocks [0, 4096):      A_pooled — one A-row per block
//   blocks [4096, 6144):   X_pooled — 2 rows per block, tanh gating
// ---------------------------------------------------------------------------
__global__ __launch_bounds__(256) void gather_kernel(
    const float* __restrict__ X, const float* __restrict__ A,
    float* __restrict__ out)
{
    cudaGridDependencySynchronize();   // PDL: wait for select completion

    int bid = blockIdx.x;
    int tid = threadIdx.x;
    if (bid < G_A) {
        int r = bid;
        const float* rowp = A + (size_t)g_idx[r] * N_ROWS;
        const int4* idx4 = (const int4*)g_idx;
        float4* o = (float4*)(out + (size_t)K_KEEP * F_DIM + (size_t)r * K_KEEP);
#pragma unroll 4
        for (int it = 0; it < 4; it++) {
            int c = tid + it * 256;
            int4 i = __ldg(&idx4[c]);
            float4 v;
            v.x = __ldg(&rowp[i.x]);
            v.y = __ldg(&rowp[i.y]);
            v.z = __ldg(&rowp[i.z]);
            v.w = __ldg(&rowp[i.w]);
            o[c] = v;
        }
    } else {
        int r   = (bid - G_A) * 2 + (tid >> 7);
        int t   = tid & 127;
        int row = g_idx[r];
        float gate = tanhf(g_y[row] * g_inv_norm);
        const float4* xr = (const float4*)(X + (size_t)row * F_DIM);
        float4* o = (float4*)(out + (size_t)r * F_DIM);
        float4 x = xr[t];
        o[t] = make_float4(x.x * gate, x.y * gate, x.z * gate, x.w * gate);
    }
}

// ---------------------------------------------------------------------------
extern "C" void kernel_launch(void* const* d_in, const int* in_sizes, int n_in,
                              void* d_out, int out_size)
{
    const float* X    = (const float*)d_in[0];
    const float* A    = (const float*)d_in[1];
    const float* kern = (const float*)d_in[2];
    float* out = (float*)d_out;

    // Kernel 1: normal launch
    compute_y_kernel<<<N_ROWS / 8, 256>>>(X, kern);

    // Kernels 2 and 3: programmatic dependent launch (pre-launch + gridsync)
    cudaLaunchAttribute attr[1];
    attr[0].id = cudaLaunchAttributeProgrammaticStreamSerialization;
    attr[0].val.programmaticStreamSerializationAllowed = 1;

    {
        cudaLaunchConfig_t cfg = {};
        cfg.gridDim  = dim3(1, 1, 1);
        cfg.blockDim = dim3(1024, 1, 1);
        cfg.attrs    = attr;
        cfg.numAttrs = 1;
        cudaLaunchKernelEx(&cfg, select_kernel, kern);
    }
    {
        cudaLaunchConfig_t cfg = {};
        cfg.gridDim  = dim3(GRID2, 1, 1);
        cfg.blockDim = dim3(256, 1, 1);
        cfg.attrs    = attr;
        cfg.numAttrs = 1;
        cudaLaunchKernelEx(&cfg, gather_kernel, X, A, out);
    }
}